// round 2
// baseline (speedup 1.0000x reference)
#include <cuda_runtime.h>
#include <math.h>

// ---------------------------------------------------------------------------
// Problem constants (match reference setup_inputs; runtime values derived from
// in_sizes and passed as kernel args, static buffers sized for these shapes).
// ---------------------------------------------------------------------------
#define D        32
#define NU_C     100001
#define NI_C     50001
#define NTOT_C   (NU_C + NI_C)        // 150002
#define BMAX     4096

// ---------------------------------------------------------------------------
// Device scratch (static __device__ globals; no allocations anywhere).
// ---------------------------------------------------------------------------
__device__ float g_emb [NTOT_C * D];   // all_emb = concat(user, item)
__device__ float g_nxt [NTOT_C * D];   // layer-1 output
__device__ float g_cur [NTOT_C * D];   // layer-2 output
__device__ float g_acc [NTOT_C * D];   // lightgcn result (ce / de)
__device__ float g_ae  [NTOT_C * D];   // ae result (kept as input to de)
__device__ float g_dinv[NTOT_C];       // per-graph deg -> d^-1/2 (in place)
__device__ float g_dtgt[NTOT_C];       // target-graph d^-1/2 (computed once)
// score slots: CP=0 CN=1 AP=2 AN=3 DP=4 DN=5; offset = (slot*2 + idx)*BMAX + b
__device__ float g_sc  [12 * BMAX];
// scalars: [0],[1] = aux log-sigmoid sums (idx 0/1); [2],[3] = sumsq user/item
__device__ float g_scal[4];

// ---------------------------------------------------------------------------
// Device helpers
// ---------------------------------------------------------------------------
__device__ __forceinline__ float logsig(float x) {
    // numerically stable log(sigmoid(x))
    return (x >= 0.f) ? -log1pf(expf(-x)) : (x - log1pf(expf(x)));
}

__device__ __forceinline__ void red4(float* p, float a, float b, float c, float d) {
    asm volatile("red.global.add.v4.f32 [%0], {%1,%2,%3,%4};"
                 :: "l"(p), "f"(a), "f"(b), "f"(c), "f"(d) : "memory");
}

// ---------------------------------------------------------------------------
// Kernels
// ---------------------------------------------------------------------------
__global__ void k_degree(const int2* __restrict__ e, int E, float* __restrict__ deg, int nu) {
    int t = blockIdx.x * blockDim.x + threadIdx.x;
    if (t < E) {
        int2 ed = e[t];
        atomicAdd(&deg[ed.x], 1.f);
        atomicAdd(&deg[nu + ed.y], 1.f);
    }
}

__global__ void k_dinv(float* __restrict__ d, int n) {
    int i = blockIdx.x * blockDim.x + threadIdx.x;
    if (i < n) {
        float x = d[i];
        d[i] = (x > 0.f) ? rsqrtf(x) : 0.f;
    }
}

// One thread handles one (edge, 16B chunk) pair: 8 threads per edge.
// Gathers src rows for both directions, vector-reduces into dst rows.
__global__ void k_prop(const int2* __restrict__ e, int E,
                       const float* __restrict__ dinv,
                       const float* __restrict__ cur,
                       float* __restrict__ nxt, int nu) {
    unsigned t  = blockIdx.x * blockDim.x + threadIdx.x;
    unsigned ei = t >> 3;
    if (ei >= (unsigned)E) return;
    int c  = (int)(t & 7u) << 2;
    int2 ed = __ldg(&e[ei]);
    int u = ed.x;
    int v = nu + ed.y;
    float w = __ldg(&dinv[u]) * __ldg(&dinv[v]);
    const float4 fu = *(const float4*)(cur + (size_t)u * D + c);
    const float4 fv = *(const float4*)(cur + (size_t)v * D + c);
    red4(nxt + (size_t)v * D + c, w * fu.x, w * fu.y, w * fu.z, w * fu.w);
    red4(nxt + (size_t)u * D + c, w * fv.x, w * fv.y, w * fv.z, w * fv.w);
}

// out = (a + b + c) / 3, vectorized (nelem multiple of 4)
__global__ void k_combine3(float* __restrict__ out,
                           const float* __restrict__ a,
                           const float* __restrict__ b,
                           const float* __restrict__ c, int n4) {
    int i = blockIdx.x * blockDim.x + threadIdx.x;
    if (i < n4) {
        float4 fa = ((const float4*)a)[i];
        float4 fb = ((const float4*)b)[i];
        float4 fc = ((const float4*)c)[i];
        float4 o;
        const float s = 1.f / 3.f;
        o.x = (fa.x + fb.x + fc.x) * s;
        o.y = (fa.y + fb.y + fc.y) * s;
        o.z = (fa.z + fb.z + fc.z) * s;
        o.w = (fa.w + fb.w + fc.w) * s;
        ((float4*)out)[i] = o;
    }
}

// warp per batch row: relu(dot) scores for (user, p_item) and (user, n_item)
__global__ void k_scores(const float* __restrict__ emb,
                         const int* __restrict__ batch, int B, int nu,
                         float* __restrict__ outp, float* __restrict__ outn) {
    int warp = (blockIdx.x * blockDim.x + threadIdx.x) >> 5;
    int lane = threadIdx.x & 31;
    if (warp >= B) return;
    const int* row = batch + (size_t)warp * 9;
    int u = row[0], p = row[1], n = row[2];
    float eu = emb[(size_t)u * D + lane];
    float pp = eu * emb[(size_t)(nu + p) * D + lane];
    float nn = eu * emb[(size_t)(nu + n) * D + lane];
    #pragma unroll
    for (int o = 16; o; o >>= 1) {
        pp += __shfl_xor_sync(0xffffffffu, pp, o);
        nn += __shfl_xor_sync(0xffffffffu, nn, o);
    }
    if (lane == 0) {
        outp[warp] = fmaxf(pp, 0.f);
        outn[warp] = fmaxf(nn, 0.f);
    }
}

// warp per batch row: accumulate sum_b log_sigmoid(ps - ns) for aux graph idx
__global__ void k_auxloss(const float* __restrict__ emb,
                          const int* __restrict__ batch, int B, int nu, int idx) {
    __shared__ float sh[8];
    int gwarp = (blockIdx.x * blockDim.x + threadIdx.x) >> 5;
    int lane  = threadIdx.x & 31;
    int wid   = threadIdx.x >> 5;
    float val = 0.f;
    if (gwarp < B) {
        const int* row = batch + (size_t)gwarp * 9 + (1 + idx) * 3;
        int u = row[0], p = row[1], n = row[2];
        float eu = emb[(size_t)u * D + lane];
        float ps = eu * emb[(size_t)(nu + p) * D + lane];
        float ns = eu * emb[(size_t)(nu + n) * D + lane];
        #pragma unroll
        for (int o = 16; o; o >>= 1) {
            ps += __shfl_xor_sync(0xffffffffu, ps, o);
            ns += __shfl_xor_sync(0xffffffffu, ns, o);
        }
        val = logsig(ps - ns);
    }
    if (lane == 0) sh[wid] = val;
    __syncthreads();
    if (threadIdx.x < 32) {
        float v = (threadIdx.x < (blockDim.x >> 5)) ? sh[threadIdx.x] : 0.f;
        #pragma unroll
        for (int o = 16; o; o >>= 1) v += __shfl_xor_sync(0xffffffffu, v, o);
        if (threadIdx.x == 0) atomicAdd(&g_scal[idx], v);
    }
}

__global__ void k_sumsq(const float* __restrict__ x, int n, int slot) {
    __shared__ float sh[8];
    float local = 0.f;
    for (int i = blockIdx.x * blockDim.x + threadIdx.x; i < n; i += gridDim.x * blockDim.x) {
        float v = x[i];
        local += v * v;
    }
    int lane = threadIdx.x & 31, wid = threadIdx.x >> 5;
    #pragma unroll
    for (int o = 16; o; o >>= 1) local += __shfl_xor_sync(0xffffffffu, local, o);
    if (lane == 0) sh[wid] = local;
    __syncthreads();
    if (threadIdx.x < 32) {
        float v = (threadIdx.x < (blockDim.x >> 5)) ? sh[threadIdx.x] : 0.f;
        #pragma unroll
        for (int o = 16; o; o >>= 1) v += __shfl_xor_sync(0xffffffffu, v, o);
        if (threadIdx.x == 0) atomicAdd(&g_scal[slot], v);
    }
}

// single block: front-door combine + rec loss + aux loss + emb loss -> out[0]
__global__ void k_final(int B, int ni, float* __restrict__ out) {
    __shared__ float sh[8];
    float local = 0.f;
    for (int b = threadIdx.x; b < B; b += blockDim.x) {
        float cp0 = g_sc[ 0 * BMAX + b], cp1 = g_sc[ 1 * BMAX + b];
        float cn0 = g_sc[ 2 * BMAX + b], cn1 = g_sc[ 3 * BMAX + b];
        float ap0 = g_sc[ 4 * BMAX + b], ap1 = g_sc[ 5 * BMAX + b];
        float an0 = g_sc[ 6 * BMAX + b], an1 = g_sc[ 7 * BMAX + b];
        float dp0 = g_sc[ 8 * BMAX + b], dp1 = g_sc[ 9 * BMAX + b];
        float dn0 = g_sc[10 * BMAX + b], dn1 = g_sc[11 * BMAX + b];
        float ps = (dp0 + dp1) * (cp0 * ap0 + cp1 * ap1);
        float ns = (dn0 + dn1) * (cn0 * an0 + cn1 * an1);
        local += logsig(ps - ns);
    }
    int lane = threadIdx.x & 31, wid = threadIdx.x >> 5;
    #pragma unroll
    for (int o = 16; o; o >>= 1) local += __shfl_xor_sync(0xffffffffu, local, o);
    if (lane == 0) sh[wid] = local;
    __syncthreads();
    if (threadIdx.x == 0) {
        float s = 0.f;
        for (int i = 0; i < (int)(blockDim.x >> 5); i++) s += sh[i];
        float rec  = -s / (float)B;
        float aux  = -(g_scal[0] + g_scal[1]) / (2.f * (float)B);
        float embl = (sqrtf(g_scal[2]) + sqrtf(g_scal[3])) / (float)ni;
        out[0] = rec + 0.5f * aux + 1e-4f * embl;
    }
}

// ---------------------------------------------------------------------------
// Host orchestration (graph-capturable: kernels + async memset/memcpy only)
// ---------------------------------------------------------------------------
#define TB 256
static inline int nblk(long long n) { return (int)((n + TB - 1) / TB); }

extern "C" void kernel_launch(void* const* d_in, const int* in_sizes, int n_in,
                              void* d_out, int out_size) {
    const float* user  = (const float*)d_in[0];
    const float* item  = (const float*)d_in[1];
    const int*   batch = (const int*)  d_in[2];
    const int2*  aux   = (const int2*) d_in[3];
    const int2*  tgt   = (const int2*) d_in[4];

    const int nu   = in_sizes[0] / D;       // 100001
    const int ni   = in_sizes[1] / D;       // 50001
    const int ntot = nu + ni;               // 150002
    const int B    = in_sizes[2] / 9;       // 4096
    const int Ea   = in_sizes[3] / 4;       // edges per aux graph (2 graphs, int2)
    const int Et   = in_sizes[4] / 2;       // target edges

    float *emb, *nxt, *cur, *acc, *ae, *dinv, *dtgt, *sc;
    void* p;
    cudaGetSymbolAddress(&p, g_emb);  emb  = (float*)p;
    cudaGetSymbolAddress(&p, g_nxt);  nxt  = (float*)p;
    cudaGetSymbolAddress(&p, g_cur);  cur  = (float*)p;
    cudaGetSymbolAddress(&p, g_acc);  acc  = (float*)p;
    cudaGetSymbolAddress(&p, g_ae);   ae   = (float*)p;
    cudaGetSymbolAddress(&p, g_dinv); dinv = (float*)p;
    cudaGetSymbolAddress(&p, g_dtgt); dtgt = (float*)p;
    cudaGetSymbolAddress(&p, g_sc);   sc   = (float*)p;
    void* scalp; cudaGetSymbolAddress(&scalp, g_scal);

    const size_t nelem = (size_t)ntot * D;
    const int n4 = (int)(nelem / 4);

    // init: all_emb, scalars, embedding norms
    cudaMemcpyAsync(emb, user, (size_t)nu * D * sizeof(float), cudaMemcpyDeviceToDevice, 0);
    cudaMemcpyAsync(emb + (size_t)nu * D, item, (size_t)ni * D * sizeof(float),
                    cudaMemcpyDeviceToDevice, 0);
    cudaMemsetAsync(scalp, 0, 4 * sizeof(float), 0);
    k_sumsq<<<1024, TB>>>(user, nu * D, 2);
    k_sumsq<<<1024, TB>>>(item, ni * D, 3);

    // target-graph dinv (reused for both de computations)
    cudaMemsetAsync(dtgt, 0, ntot * sizeof(float), 0);
    k_degree<<<nblk(Et), TB>>>(tgt, Et, dtgt, nu);
    k_dinv<<<nblk(ntot), TB>>>(dtgt, ntot);

    // 2-layer lightgcn: out = (src + L*src + L^2*src)/3 over up to two edge lists
    auto lightgcn = [&](const float* src, const float* dv,
                        const int2* e1, int E1, const int2* e2, int E2, float* out) {
        cudaMemsetAsync(nxt, 0, nelem * sizeof(float), 0);
        k_prop<<<nblk((long long)E1 * 8), TB>>>(e1, E1, dv, src, nxt, nu);
        if (e2) k_prop<<<nblk((long long)E2 * 8), TB>>>(e2, E2, dv, src, nxt, nu);
        cudaMemsetAsync(cur, 0, nelem * sizeof(float), 0);
        k_prop<<<nblk((long long)E1 * 8), TB>>>(e1, E1, dv, nxt, cur, nu);
        if (e2) k_prop<<<nblk((long long)E2 * 8), TB>>>(e2, E2, dv, nxt, cur, nu);
        k_combine3<<<nblk(n4), TB>>>(out, src, nxt, cur, n4);
    };

    const int sblk = nblk((long long)B * 32);

    for (int idx = 0; idx < 2; idx++) {
        const int2* ax = aux + (size_t)idx * Ea;

        // --- combined graph (aux[idx] + target): ce -> cp/cn ---
        cudaMemsetAsync(dinv, 0, ntot * sizeof(float), 0);
        k_degree<<<nblk(Ea), TB>>>(ax, Ea, dinv, nu);
        k_degree<<<nblk(Et), TB>>>(tgt, Et, dinv, nu);
        k_dinv<<<nblk(ntot), TB>>>(dinv, ntot);
        lightgcn(emb, dinv, ax, Ea, tgt, Et, acc);
        k_scores<<<sblk, TB>>>(acc, batch, B, nu,
                               sc + (0 * 2 + idx) * BMAX,    // CP
                               sc + (1 * 2 + idx) * BMAX);   // CN

        // --- aux graph alone: ae -> ap/an + aux BPR ---
        cudaMemsetAsync(dinv, 0, ntot * sizeof(float), 0);
        k_degree<<<nblk(Ea), TB>>>(ax, Ea, dinv, nu);
        k_dinv<<<nblk(ntot), TB>>>(dinv, ntot);
        lightgcn(emb, dinv, ax, Ea, (const int2*)0, 0, ae);
        k_scores<<<sblk, TB>>>(ae, batch, B, nu,
                               sc + (2 * 2 + idx) * BMAX,    // AP
                               sc + (3 * 2 + idx) * BMAX);   // AN
        k_auxloss<<<sblk, TB>>>(ae, batch, B, nu, idx);

        // --- de = lightgcn(ae, target graph) -> dp/dn ---
        lightgcn(ae, dtgt, tgt, Et, (const int2*)0, 0, acc);
        k_scores<<<sblk, TB>>>(acc, batch, B, nu,
                               sc + (4 * 2 + idx) * BMAX,    // DP
                               sc + (5 * 2 + idx) * BMAX);   // DN
    }

    k_final<<<1, TB>>>(B, ni, (float*)d_out);
}

// round 3
// speedup vs baseline: 1.2190x; 1.2190x over previous
#include <cuda_runtime.h>
#include <math.h>

// ---------------------------------------------------------------------------
// Shapes (static buffers sized for the dataset; runtime values from in_sizes)
// ---------------------------------------------------------------------------
#define D        32
#define NU_C     100001
#define NI_C     50001
#define NTOT_C   (NU_C + NI_C)          // 150002
#define NOFF     (NTOT_C + 1)
#define BMAX     4096
#define SCAN_B   256
#define NBLK_SCAN ((NOFF + SCAN_B - 1) / SCAN_B)   // 587
#define SUMS_STRIDE 640
#define CSR_CAP  14400000               // directed entries across all 5 graphs

// ---------------------------------------------------------------------------
// Device scratch (static; no allocations anywhere)
// ---------------------------------------------------------------------------
__device__ float g_emb[NTOT_C * D];     // concat(user, item)
__device__ float g_nxt[NTOT_C * D];     // layer-1 scratch (comb / de)
__device__ float g_nx2[NTOT_C * D];     // layer-1 scratch (aux)
__device__ float g_ae [NTOT_C * D];     // ae result
__device__ int   g_degi [5 * NTOT_C];   // integer degrees, slots: comb0,comb1,aux0,aux1,tgt
__device__ float g_dnv  [5 * NTOT_C];   // d^-1/2 per graph
__device__ int   g_off  [5 * NOFF];     // CSR offsets (local per graph)
__device__ int   g_curs [5 * NOFF];     // fill cursors
__device__ int   g_bsums[5 * SUMS_STRIDE];
__device__ int2  g_csr  [CSR_CAP];      // {src_node, weight-as-int} entries
// score slots: CP=0 CN=1 AP=2 AN=3 DP=4 DN=5; offset = (slot*2 + idx)*BMAX + b
__device__ float g_sc  [12 * BMAX];
// scalars: [0],[1] aux log-sigmoid sums; [2],[3] sumsq user/item
__device__ float g_scal[4];

// ---------------------------------------------------------------------------
// Helpers
// ---------------------------------------------------------------------------
__device__ __forceinline__ float logsig(float x) {
    return (x >= 0.f) ? -log1pf(expf(-x)) : (x - log1pf(expf(x)));
}

// warp-cooperative gather: sum_j w_j * src[adj_j][lane], unrolled for MLP
__device__ __forceinline__ float gather_row(const int2* __restrict__ csr,
                                            int k, int end,
                                            const float* __restrict__ src,
                                            int lane) {
    float acc = 0.f;
    for (; k + 8 <= end; k += 8) {
        int2 e[8];
        #pragma unroll
        for (int j = 0; j < 8; j++) e[j] = __ldg(&csr[k + j]);
        #pragma unroll
        for (int j = 0; j < 8; j++) {
            float v = __ldg(&src[(size_t)e[j].x * D + lane]);
            acc = fmaf(__int_as_float(e[j].y), v, acc);
        }
    }
    if (k + 4 <= end) {
        int2 e[4];
        #pragma unroll
        for (int j = 0; j < 4; j++) e[j] = __ldg(&csr[k + j]);
        #pragma unroll
        for (int j = 0; j < 4; j++) {
            float v = __ldg(&src[(size_t)e[j].x * D + lane]);
            acc = fmaf(__int_as_float(e[j].y), v, acc);
        }
        k += 4;
    }
    for (; k < end; k++) {
        int2 e = __ldg(&csr[k]);
        acc = fmaf(__int_as_float(e.y), __ldg(&src[(size_t)e.x * D + lane]), acc);
    }
    return acc;
}

// ---------------------------------------------------------------------------
// Graph build kernels
// ---------------------------------------------------------------------------
__global__ void k_degi(const int2* __restrict__ e, int E, int* __restrict__ deg, int nu) {
    int t = blockIdx.x * blockDim.x + threadIdx.x;
    if (t < E) {
        int2 ed = e[t];
        atomicAdd(&deg[ed.x], 1);
        atomicAdd(&deg[nu + ed.y], 1);
    }
}

__global__ void k_dinv5() {
    int i = blockIdx.x * blockDim.x + threadIdx.x;
    if (i >= NTOT_C) return;
    int d2 = g_degi[2 * NTOT_C + i];
    int d3 = g_degi[3 * NTOT_C + i];
    int d4 = g_degi[4 * NTOT_C + i];
    g_degi[0 * NTOT_C + i] = d2 + d4;   // comb0 = aux0 + tgt
    g_degi[1 * NTOT_C + i] = d3 + d4;   // comb1 = aux1 + tgt
    int dd[5] = {d2 + d4, d3 + d4, d2, d3, d4};
    #pragma unroll
    for (int s = 0; s < 5; s++)
        g_dnv[s * NTOT_C + i] = (dd[s] > 0) ? rsqrtf((float)dd[s]) : 0.f;
}

// --- exclusive scan of degrees -> offsets (batched over 5 graphs via grid.y)
__global__ void k_scanA() {
    int g = blockIdx.y;
    const int* deg = g_degi + g * NTOT_C;
    int* out  = g_off   + g * NOFF;
    int* sums = g_bsums + g * SUMS_STRIDE;
    int idx = blockIdx.x * SCAN_B + threadIdx.x;
    int val = (idx < NTOT_C) ? deg[idx] : 0;     // idx==NTOT_C reads 0
    int lane = threadIdx.x & 31, wid = threadIdx.x >> 5;
    int x = val;
    #pragma unroll
    for (int o = 1; o < 32; o <<= 1) {
        int y = __shfl_up_sync(0xffffffffu, x, o);
        if (lane >= o) x += y;
    }
    __shared__ int ws[8], wbase[8];
    if (lane == 31) ws[wid] = x;
    __syncthreads();
    if (threadIdx.x == 0) {
        int s = 0;
        for (int i = 0; i < 8; i++) { wbase[i] = s; s += ws[i]; }
    }
    __syncthreads();
    int incl = x + wbase[wid];
    if (idx < NOFF) out[idx] = incl - val;       // exclusive
    if (threadIdx.x == SCAN_B - 1) sums[blockIdx.x] = incl;
}

__global__ void k_scanB(int nb) {
    int g = blockIdx.x;
    int* sums = g_bsums + g * SUMS_STRIDE;
    __shared__ int sh[SUMS_STRIDE];
    int tid = threadIdx.x;
    int orig = 0;
    if (tid < nb) { orig = sums[tid]; sh[tid] = orig; }
    __syncthreads();
    for (int o = 1; o < nb; o <<= 1) {
        int v = 0;
        if (tid < nb && tid >= o) v = sh[tid - o];
        __syncthreads();
        if (tid < nb && tid >= o) sh[tid] += v;
        __syncthreads();
    }
    if (tid < nb) sums[tid] = sh[tid] - orig;    // exclusive
}

__global__ void k_scanC() {
    int g = blockIdx.y;
    int idx = blockIdx.x * SCAN_B + threadIdx.x;
    if (idx < NOFF)
        g_off[g * NOFF + idx] += g_bsums[g * SUMS_STRIDE + blockIdx.x];
}

__global__ void k_fill(const int2* __restrict__ e, int E,
                       const float* __restrict__ dnv,
                       int* __restrict__ curs, int2* __restrict__ csr, int nu) {
    int t = blockIdx.x * blockDim.x + threadIdx.x;
    if (t >= E) return;
    int2 ed = e[t];
    int u = ed.x, v = nu + ed.y;
    float w = dnv[u] * dnv[v];
    int2 a; a.y = __float_as_int(w);
    int p1 = atomicAdd(&curs[u], 1); a.x = v; csr[p1] = a;
    int p2 = atomicAdd(&curs[v], 1); a.x = u; csr[p2] = a;
}

// ---------------------------------------------------------------------------
// Propagation
// ---------------------------------------------------------------------------
// base==null : out[n] = sum_j w_j src[adj_j]                 (layer 1)
// base!=null : out[n] = (base[n] + src[n] + gather(n)) / 3   (layer 2 + mean)
__global__ void k_gcn(const int2* __restrict__ csr, const int* __restrict__ off,
                      const float* __restrict__ src, float* __restrict__ out,
                      const float* __restrict__ base, int ntot) {
    int w = (blockIdx.x * blockDim.x + threadIdx.x) >> 5;
    if (w >= ntot) return;
    int lane = threadIdx.x & 31;
    float acc = gather_row(csr, off[w], off[w + 1], src, lane);
    size_t o = (size_t)w * D + lane;
    if (base) acc = (acc + src[o] + base[o]) * (1.f / 3.f);
    out[o] = acc;
}

// fused sparse layer-2 + combine + relu(dot): only the 3 batch rows per b.
// row r = (base[r] + nxt[r] + gather_nxt(r)); dot scaled by 1/9 at the end.
__global__ void k_score_l2(const int2* __restrict__ csr, const int* __restrict__ off,
                           const float* __restrict__ nxt, const float* __restrict__ base,
                           const int* __restrict__ batch, int B, int nu,
                           float* __restrict__ outp, float* __restrict__ outn) {
    int wp = (blockIdx.x * blockDim.x + threadIdx.x) >> 5;
    if (wp >= B) return;
    int lane = threadIdx.x & 31;
    const int* row = batch + (size_t)wp * 9;
    int u = row[0], p = nu + row[1], n = nu + row[2];
    float eu = base[(size_t)u * D + lane] + nxt[(size_t)u * D + lane]
             + gather_row(csr, off[u], off[u + 1], nxt, lane);
    float ep = base[(size_t)p * D + lane] + nxt[(size_t)p * D + lane]
             + gather_row(csr, off[p], off[p + 1], nxt, lane);
    float en = base[(size_t)n * D + lane] + nxt[(size_t)n * D + lane]
             + gather_row(csr, off[n], off[n + 1], nxt, lane);
    float pp = eu * ep, nn = eu * en;
    #pragma unroll
    for (int o = 16; o; o >>= 1) {
        pp += __shfl_xor_sync(0xffffffffu, pp, o);
        nn += __shfl_xor_sync(0xffffffffu, nn, o);
    }
    if (lane == 0) {
        outp[wp] = fmaxf(pp * (1.f / 9.f), 0.f);
        outn[wp] = fmaxf(nn * (1.f / 9.f), 0.f);
    }
}

// ---------------------------------------------------------------------------
// Scoring / losses
// ---------------------------------------------------------------------------
__global__ void k_scores(const float* __restrict__ emb,
                         const int* __restrict__ batch, int B, int nu,
                         float* __restrict__ outp, float* __restrict__ outn) {
    int warp = (blockIdx.x * blockDim.x + threadIdx.x) >> 5;
    int lane = threadIdx.x & 31;
    if (warp >= B) return;
    const int* row = batch + (size_t)warp * 9;
    int u = row[0], p = row[1], n = row[2];
    float eu = emb[(size_t)u * D + lane];
    float pp = eu * emb[(size_t)(nu + p) * D + lane];
    float nn = eu * emb[(size_t)(nu + n) * D + lane];
    #pragma unroll
    for (int o = 16; o; o >>= 1) {
        pp += __shfl_xor_sync(0xffffffffu, pp, o);
        nn += __shfl_xor_sync(0xffffffffu, nn, o);
    }
    if (lane == 0) {
        outp[warp] = fmaxf(pp, 0.f);
        outn[warp] = fmaxf(nn, 0.f);
    }
}

__global__ void k_auxloss(const float* __restrict__ emb,
                          const int* __restrict__ batch, int B, int nu, int idx) {
    __shared__ float sh[8];
    int gwarp = (blockIdx.x * blockDim.x + threadIdx.x) >> 5;
    int lane = threadIdx.x & 31;
    int wid = threadIdx.x >> 5;
    float val = 0.f;
    if (gwarp < B) {
        const int* row = batch + (size_t)gwarp * 9 + (1 + idx) * 3;
        int u = row[0], p = row[1], n = row[2];
        float eu = emb[(size_t)u * D + lane];
        float ps = eu * emb[(size_t)(nu + p) * D + lane];
        float ns = eu * emb[(size_t)(nu + n) * D + lane];
        #pragma unroll
        for (int o = 16; o; o >>= 1) {
            ps += __shfl_xor_sync(0xffffffffu, ps, o);
            ns += __shfl_xor_sync(0xffffffffu, ns, o);
        }
        val = logsig(ps - ns);
    }
    if (lane == 0) sh[wid] = val;
    __syncthreads();
    if (threadIdx.x < 32) {
        float v = (threadIdx.x < (blockDim.x >> 5)) ? sh[threadIdx.x] : 0.f;
        #pragma unroll
        for (int o = 16; o; o >>= 1) v += __shfl_xor_sync(0xffffffffu, v, o);
        if (threadIdx.x == 0) atomicAdd(&g_scal[idx], v);
    }
}

__global__ void k_sumsq(const float* __restrict__ x, int n, int slot) {
    __shared__ float sh[8];
    float local = 0.f;
    for (int i = blockIdx.x * blockDim.x + threadIdx.x; i < n; i += gridDim.x * blockDim.x) {
        float v = x[i];
        local += v * v;
    }
    int lane = threadIdx.x & 31, wid = threadIdx.x >> 5;
    #pragma unroll
    for (int o = 16; o; o >>= 1) local += __shfl_xor_sync(0xffffffffu, local, o);
    if (lane == 0) sh[wid] = local;
    __syncthreads();
    if (threadIdx.x < 32) {
        float v = (threadIdx.x < (blockDim.x >> 5)) ? sh[threadIdx.x] : 0.f;
        #pragma unroll
        for (int o = 16; o; o >>= 1) v += __shfl_xor_sync(0xffffffffu, v, o);
        if (threadIdx.x == 0) atomicAdd(&g_scal[slot], v);
    }
}

__global__ void k_final(int B, int ni, float* __restrict__ out) {
    __shared__ float sh[8];
    float local = 0.f;
    for (int b = threadIdx.x; b < B; b += blockDim.x) {
        float cp0 = g_sc[ 0 * BMAX + b], cp1 = g_sc[ 1 * BMAX + b];
        float cn0 = g_sc[ 2 * BMAX + b], cn1 = g_sc[ 3 * BMAX + b];
        float ap0 = g_sc[ 4 * BMAX + b], ap1 = g_sc[ 5 * BMAX + b];
        float an0 = g_sc[ 6 * BMAX + b], an1 = g_sc[ 7 * BMAX + b];
        float dp0 = g_sc[ 8 * BMAX + b], dp1 = g_sc[ 9 * BMAX + b];
        float dn0 = g_sc[10 * BMAX + b], dn1 = g_sc[11 * BMAX + b];
        float ps = (dp0 + dp1) * (cp0 * ap0 + cp1 * ap1);
        float ns = (dn0 + dn1) * (cn0 * an0 + cn1 * an1);
        local += logsig(ps - ns);
    }
    int lane = threadIdx.x & 31, wid = threadIdx.x >> 5;
    #pragma unroll
    for (int o = 16; o; o >>= 1) local += __shfl_xor_sync(0xffffffffu, local, o);
    if (lane == 0) sh[wid] = local;
    __syncthreads();
    if (threadIdx.x == 0) {
        float s = 0.f;
        for (int i = 0; i < (int)(blockDim.x >> 5); i++) s += sh[i];
        float rec  = -s / (float)B;
        float aux  = -(g_scal[0] + g_scal[1]) / (2.f * (float)B);
        float embl = (sqrtf(g_scal[2]) + sqrtf(g_scal[3])) / (float)ni;
        out[0] = rec + 0.5f * aux + 1e-4f * embl;
    }
}

// ---------------------------------------------------------------------------
// Host orchestration (graph-capturable)
// ---------------------------------------------------------------------------
#define TB 256
static inline int nblk(long long n) { return (int)((n + TB - 1) / TB); }

extern "C" void kernel_launch(void* const* d_in, const int* in_sizes, int n_in,
                              void* d_out, int out_size) {
    const float* user  = (const float*)d_in[0];
    const float* item  = (const float*)d_in[1];
    const int*   batch = (const int*)  d_in[2];
    const int2*  aux   = (const int2*) d_in[3];
    const int2*  tgt   = (const int2*) d_in[4];

    const int nu   = in_sizes[0] / D;       // 100001
    const int ni   = in_sizes[1] / D;       // 50001
    const int ntot = nu + ni;
    const int B    = in_sizes[2] / 9;       // 4096
    const int Ea   = in_sizes[3] / 4;       // edges per aux graph
    const int Et   = in_sizes[4] / 2;       // target edges

    float *emb, *nxt, *nx2, *ae, *dnv, *sc;
    int *degi, *off, *curs;
    int2 *csr;
    void* p;
    cudaGetSymbolAddress(&p, g_emb);  emb  = (float*)p;
    cudaGetSymbolAddress(&p, g_nxt);  nxt  = (float*)p;
    cudaGetSymbolAddress(&p, g_nx2);  nx2  = (float*)p;
    cudaGetSymbolAddress(&p, g_ae);   ae   = (float*)p;
    cudaGetSymbolAddress(&p, g_dnv);  dnv  = (float*)p;
    cudaGetSymbolAddress(&p, g_sc);   sc   = (float*)p;
    cudaGetSymbolAddress(&p, g_degi); degi = (int*)p;
    cudaGetSymbolAddress(&p, g_off);  off  = (int*)p;
    cudaGetSymbolAddress(&p, g_curs); curs = (int*)p;
    cudaGetSymbolAddress(&p, g_csr);  csr  = (int2*)p;
    void* scalp; cudaGetSymbolAddress(&scalp, g_scal);

    // --- init: concat embeddings, scalars, Frobenius norms ---
    cudaMemcpyAsync(emb, user, (size_t)nu * D * sizeof(float), cudaMemcpyDeviceToDevice, 0);
    cudaMemcpyAsync(emb + (size_t)nu * D, item, (size_t)ni * D * sizeof(float),
                    cudaMemcpyDeviceToDevice, 0);
    cudaMemsetAsync(scalp, 0, 4 * sizeof(float), 0);
    k_sumsq<<<1024, TB>>>(user, nu * D, 2);
    k_sumsq<<<1024, TB>>>(item, ni * D, 3);

    // --- degrees (aux0 -> slot2, aux1 -> slot3, tgt -> slot4) ---
    cudaMemsetAsync(degi + 2 * NTOT_C, 0, 3 * NTOT_C * sizeof(int), 0);
    k_degi<<<nblk(Ea), TB>>>(aux,            Ea, degi + 2 * NTOT_C, nu);
    k_degi<<<nblk(Ea), TB>>>(aux + Ea,       Ea, degi + 3 * NTOT_C, nu);
    k_degi<<<nblk(Et), TB>>>(tgt,            Et, degi + 4 * NTOT_C, nu);
    k_dinv5<<<nblk(NTOT_C), TB>>>();

    // --- offsets via batched exclusive scan over 5 graphs ---
    dim3 gScan(NBLK_SCAN, 5);
    k_scanA<<<gScan, SCAN_B>>>();
    k_scanB<<<5, 1024>>>(NBLK_SCAN);
    k_scanC<<<gScan, SCAN_B>>>();
    cudaMemcpyAsync(curs, off, 5 * NOFF * sizeof(int), cudaMemcpyDeviceToDevice, 0);

    // --- CSR fill (bases in the shared arena) ---
    const long long bC0 = 0;
    const long long bC1 = 2LL * (Ea + Et);
    const long long bA0 = 4LL * (Ea + Et);
    const long long bA1 = bA0 + 2LL * Ea;
    const long long bT  = bA1 + 2LL * Ea;
    k_fill<<<nblk(Ea), TB>>>(aux,      Ea, dnv + 2 * NTOT_C, curs + 2 * NOFF, csr + bA0, nu);
    k_fill<<<nblk(Ea), TB>>>(aux + Ea, Ea, dnv + 3 * NTOT_C, curs + 3 * NOFF, csr + bA1, nu);
    k_fill<<<nblk(Et), TB>>>(tgt,      Et, dnv + 4 * NTOT_C, curs + 4 * NOFF, csr + bT,  nu);
    k_fill<<<nblk(Ea), TB>>>(aux,      Ea, dnv + 0 * NTOT_C, curs + 0 * NOFF, csr + bC0, nu);
    k_fill<<<nblk(Et), TB>>>(tgt,      Et, dnv + 0 * NTOT_C, curs + 0 * NOFF, csr + bC0, nu);
    k_fill<<<nblk(Ea), TB>>>(aux + Ea, Ea, dnv + 1 * NTOT_C, curs + 1 * NOFF, csr + bC1, nu);
    k_fill<<<nblk(Et), TB>>>(tgt,      Et, dnv + 1 * NTOT_C, curs + 1 * NOFF, csr + bC1, nu);

    const int gcnB = nblk((long long)ntot * 32);
    const int sblk = nblk((long long)B * 32);

    for (int idx = 0; idx < 2; idx++) {
        const int2* csrC = csr + (idx ? bC1 : bC0);
        const int*  offC = off + idx * NOFF;
        const int2* csrA = csr + (idx ? bA1 : bA0);
        const int*  offA = off + (2 + idx) * NOFF;
        const int2* csrT = csr + bT;
        const int*  offT = off + 4 * NOFF;

        // combined graph: layer1 full, layer2 fused into scores (CP/CN)
        k_gcn<<<gcnB, TB>>>(csrC, offC, emb, nxt, (const float*)0, ntot);
        k_score_l2<<<sblk, TB>>>(csrC, offC, nxt, emb, batch, B, nu,
                                 sc + (0 * 2 + idx) * BMAX, sc + (1 * 2 + idx) * BMAX);

        // aux graph: full two layers -> ae (needed densely)
        k_gcn<<<gcnB, TB>>>(csrA, offA, emb, nx2, (const float*)0, ntot);
        k_gcn<<<gcnB, TB>>>(csrA, offA, nx2, ae, emb, ntot);
        k_scores<<<sblk, TB>>>(ae, batch, B, nu,
                               sc + (2 * 2 + idx) * BMAX, sc + (3 * 2 + idx) * BMAX);
        k_auxloss<<<sblk, TB>>>(ae, batch, B, nu, idx);

        // de = lightgcn(ae, tgt): layer1 full, layer2 fused into scores (DP/DN)
        k_gcn<<<gcnB, TB>>>(csrT, offT, ae, nxt, (const float*)0, ntot);
        k_score_l2<<<sblk, TB>>>(csrT, offT, nxt, ae, batch, B, nu,
                                 sc + (4 * 2 + idx) * BMAX, sc + (5 * 2 + idx) * BMAX);
    }

    k_final<<<1, TB>>>(B, ni, (float*)d_out);
}

// round 4
// speedup vs baseline: 1.6085x; 1.3196x over previous
#include <cuda_runtime.h>
#include <math.h>

// ---------------------------------------------------------------------------
// Shapes
// ---------------------------------------------------------------------------
#define D        32
#define NU_C     100001
#define NI_C     50001
#define NTOT_C   (NU_C + NI_C)          // 150002
#define NOFF     (NTOT_C + 1)
#define BMAX     4096
#define SCAN_B   256
#define NBLK_SCAN ((NOFF + SCAN_B - 1) / SCAN_B)   // 587
#define SUMS_STRIDE 640
#define CSR_CAP  6400000                // directed entries: aux0+aux1+tgt

// ---------------------------------------------------------------------------
// Device scratch
// ---------------------------------------------------------------------------
__device__ float g_emb[NTOT_C * D];
__device__ float g_pc0[NTOT_C * D];     // comb0 layer1 (aux part, then +=tgt part)
__device__ float g_pc1[NTOT_C * D];     // comb1 layer1
__device__ float g_pt0[NTOT_C * D];     // comb0 tgt part; later ae0
__device__ float g_pt1[NTOT_C * D];     // comb1 tgt part; later ae1
__device__ float g_a0 [NTOT_C * D];     // aux0 layer1;   later de0 layer1
__device__ float g_a1 [NTOT_C * D];     // aux1 layer1;   later de1 layer1
__device__ int   g_degi [3 * NTOT_C];   // aux0, aux1, tgt
__device__ float g_dnv  [5 * NTOT_C];   // c0, c1, a0, a1, t
__device__ int   g_off  [3 * NOFF];
__device__ int   g_curs [3 * NOFF];
__device__ int   g_bsums[3 * SUMS_STRIDE];
__device__ int   g_csr  [CSR_CAP];      // neighbor indices only
// score slots: CP=0 CN=1 AP=2 AN=3 DP=4 DN=5; offset = (slot*2 + idx)*BMAX + b
__device__ float g_sc  [12 * BMAX];
__device__ float g_scal[4];             // aux sums (0,1), sumsq user/item (2,3)

// ---------------------------------------------------------------------------
// Helpers
// ---------------------------------------------------------------------------
__device__ __forceinline__ float logsig(float x) {
    return (x >= 0.f) ? -log1pf(expf(-x)) : (x - log1pf(expf(x)));
}

// weighted gather: sum_j dinv[adj_j] * src[adj_j][lane]   (caller scales by dinv[u])
__device__ __forceinline__ float gather_w(const int* __restrict__ csr,
                                          int k, int end,
                                          const float* __restrict__ dnv,
                                          const float* __restrict__ src,
                                          int lane) {
    float acc = 0.f;
    for (; k + 8 <= end; k += 8) {
        int e[8]; float w[8];
        #pragma unroll
        for (int j = 0; j < 8; j++) e[j] = __ldg(&csr[k + j]);
        #pragma unroll
        for (int j = 0; j < 8; j++) w[j] = __ldg(&dnv[e[j]]);
        #pragma unroll
        for (int j = 0; j < 8; j++)
            acc = fmaf(w[j], __ldg(&src[(size_t)e[j] * D + lane]), acc);
    }
    for (; k < end; k++) {
        int e = __ldg(&csr[k]);
        acc = fmaf(__ldg(&dnv[e]), __ldg(&src[(size_t)e * D + lane]), acc);
    }
    return acc;
}

// ---------------------------------------------------------------------------
// Graph build
// ---------------------------------------------------------------------------
__global__ void k_degi(const int2* __restrict__ e, int E, int* __restrict__ deg, int nu) {
    int t = blockIdx.x * blockDim.x + threadIdx.x;
    if (t < E) {
        int2 ed = e[t];
        atomicAdd(&deg[ed.x], 1);
        atomicAdd(&deg[nu + ed.y], 1);
    }
}

__global__ void k_dinv5() {
    int i = blockIdx.x * blockDim.x + threadIdx.x;
    if (i >= NTOT_C) return;
    int d0 = g_degi[0 * NTOT_C + i];
    int d1 = g_degi[1 * NTOT_C + i];
    int dt = g_degi[2 * NTOT_C + i];
    int dd[5] = {d0 + dt, d1 + dt, d0, d1, dt};
    #pragma unroll
    for (int s = 0; s < 5; s++)
        g_dnv[s * NTOT_C + i] = (dd[s] > 0) ? rsqrtf((float)dd[s]) : 0.f;
}

__global__ void k_scanA() {
    int g = blockIdx.y;
    const int* deg = g_degi + g * NTOT_C;
    int* out  = g_off   + g * NOFF;
    int* sums = g_bsums + g * SUMS_STRIDE;
    int idx = blockIdx.x * SCAN_B + threadIdx.x;
    int val = (idx < NTOT_C) ? deg[idx] : 0;
    int lane = threadIdx.x & 31, wid = threadIdx.x >> 5;
    int x = val;
    #pragma unroll
    for (int o = 1; o < 32; o <<= 1) {
        int y = __shfl_up_sync(0xffffffffu, x, o);
        if (lane >= o) x += y;
    }
    __shared__ int ws[8], wbase[8];
    if (lane == 31) ws[wid] = x;
    __syncthreads();
    if (threadIdx.x == 0) {
        int s = 0;
        for (int i = 0; i < 8; i++) { wbase[i] = s; s += ws[i]; }
    }
    __syncthreads();
    int incl = x + wbase[wid];
    if (idx < NOFF) out[idx] = incl - val;
    if (threadIdx.x == SCAN_B - 1) sums[blockIdx.x] = incl;
}

__global__ void k_scanB(int nb) {
    int g = blockIdx.x;
    int* sums = g_bsums + g * SUMS_STRIDE;
    __shared__ int sh[SUMS_STRIDE];
    int tid = threadIdx.x;
    int orig = 0;
    if (tid < nb) { orig = sums[tid]; sh[tid] = orig; }
    __syncthreads();
    for (int o = 1; o < nb; o <<= 1) {
        int v = 0;
        if (tid < nb && tid >= o) v = sh[tid - o];
        __syncthreads();
        if (tid < nb && tid >= o) sh[tid] += v;
        __syncthreads();
    }
    if (tid < nb) sums[tid] = sh[tid] - orig;
}

__global__ void k_scanC() {
    int g = blockIdx.y;
    int idx = blockIdx.x * SCAN_B + threadIdx.x;
    if (idx < NOFF)
        g_off[g * NOFF + idx] += g_bsums[g * SUMS_STRIDE + blockIdx.x];
}

__global__ void k_fill(const int2* __restrict__ e, int E,
                       int* __restrict__ curs, int* __restrict__ csr, int nu) {
    int t = blockIdx.x * blockDim.x + threadIdx.x;
    if (t >= E) return;
    int2 ed = e[t];
    int u = ed.x, v = nu + ed.y;
    csr[atomicAdd(&curs[u], 1)] = v;
    csr[atomicAdd(&curs[v], 1)] = u;
}

// ---------------------------------------------------------------------------
// Propagation
// ---------------------------------------------------------------------------
// One edge list, one src, two weight vectors -> two outputs.
__global__ void k_dual_w(const int* __restrict__ csr, const int* __restrict__ off,
                         const float* __restrict__ src,
                         const float* __restrict__ wX, const float* __restrict__ wY,
                         float* __restrict__ outX, float* __restrict__ outY, int ntot) {
    int u = (blockIdx.x * blockDim.x + threadIdx.x) >> 5;
    if (u >= ntot) return;
    int lane = threadIdx.x & 31;
    int k = off[u], end = off[u + 1];
    float accX = 0.f, accY = 0.f;
    for (; k + 4 <= end; k += 4) {
        int e[4]; float x[4], y[4];
        #pragma unroll
        for (int j = 0; j < 4; j++) e[j] = __ldg(&csr[k + j]);
        #pragma unroll
        for (int j = 0; j < 4; j++) { x[j] = __ldg(&wX[e[j]]); y[j] = __ldg(&wY[e[j]]); }
        #pragma unroll
        for (int j = 0; j < 4; j++) {
            float v = __ldg(&src[(size_t)e[j] * D + lane]);
            accX = fmaf(x[j], v, accX);
            accY = fmaf(y[j], v, accY);
        }
    }
    for (; k < end; k++) {
        int e = __ldg(&csr[k]);
        float v = __ldg(&src[(size_t)e * D + lane]);
        accX = fmaf(__ldg(&wX[e]), v, accX);
        accY = fmaf(__ldg(&wY[e]), v, accY);
    }
    size_t o = (size_t)u * D + lane;
    outX[o] = __ldg(&wX[u]) * accX;
    outY[o] = __ldg(&wY[u]) * accY;
}

// One edge list, one weight vector, two srcs -> two outputs (de layer1).
__global__ void k_dual_s(const int* __restrict__ csr, const int* __restrict__ off,
                         const float* __restrict__ s0, const float* __restrict__ s1,
                         const float* __restrict__ w,
                         float* __restrict__ o0, float* __restrict__ o1, int ntot) {
    int u = (blockIdx.x * blockDim.x + threadIdx.x) >> 5;
    if (u >= ntot) return;
    int lane = threadIdx.x & 31;
    int k = off[u], end = off[u + 1];
    float a0 = 0.f, a1 = 0.f;
    for (; k + 4 <= end; k += 4) {
        int e[4]; float wj[4];
        #pragma unroll
        for (int j = 0; j < 4; j++) e[j] = __ldg(&csr[k + j]);
        #pragma unroll
        for (int j = 0; j < 4; j++) wj[j] = __ldg(&w[e[j]]);
        #pragma unroll
        for (int j = 0; j < 4; j++) {
            size_t ro = (size_t)e[j] * D + lane;
            a0 = fmaf(wj[j], __ldg(&s0[ro]), a0);
            a1 = fmaf(wj[j], __ldg(&s1[ro]), a1);
        }
    }
    for (; k < end; k++) {
        int e = __ldg(&csr[k]);
        float wj = __ldg(&w[e]);
        size_t ro = (size_t)e * D + lane;
        a0 = fmaf(wj, __ldg(&s0[ro]), a0);
        a1 = fmaf(wj, __ldg(&s1[ro]), a1);
    }
    size_t o = (size_t)u * D + lane;
    float wu = __ldg(&w[u]);
    o0[o] = wu * a0;
    o1[o] = wu * a1;
}

// aux layer2 + layer-mean: out = (w[u]*gather + src[u] + base[u]) / 3
__global__ void k_gcn_w(const int* __restrict__ csr, const int* __restrict__ off,
                        const float* __restrict__ w,
                        const float* __restrict__ src, const float* __restrict__ base,
                        float* __restrict__ out, int ntot) {
    int u = (blockIdx.x * blockDim.x + threadIdx.x) >> 5;
    if (u >= ntot) return;
    int lane = threadIdx.x & 31;
    float acc = gather_w(csr, off[u], off[u + 1], w, src, lane);
    size_t o = (size_t)u * D + lane;
    out[o] = (__ldg(&w[u]) * acc + src[o] + base[o]) * (1.f / 3.f);
}

// in-place add: a += b
__global__ void k_add(float* __restrict__ a, const float* __restrict__ b, int n4) {
    int i = blockIdx.x * blockDim.x + threadIdx.x;
    if (i < n4) {
        float4 fa = ((const float4*)a)[i];
        float4 fb = ((const float4*)b)[i];
        fa.x += fb.x; fa.y += fb.y; fa.z += fb.z; fa.w += fb.w;
        ((float4*)a)[i] = fa;
    }
}

// fused sparse layer2 + combine + relu(dot); optional second edge list (comb).
__global__ void k_score2(const int* __restrict__ csr1, const int* __restrict__ off1,
                         const int* __restrict__ csr2, const int* __restrict__ off2,
                         const float* __restrict__ w,
                         const float* __restrict__ nxt, const float* __restrict__ base,
                         const int* __restrict__ batch, int B, int nu,
                         float* __restrict__ outp, float* __restrict__ outn) {
    int wp = (blockIdx.x * blockDim.x + threadIdx.x) >> 5;
    if (wp >= B) return;
    int lane = threadIdx.x & 31;
    const int* row = batch + (size_t)wp * 9;
    int nd[3] = {row[0], nu + row[1], nu + row[2]};
    float val[3];
    #pragma unroll
    for (int t = 0; t < 3; t++) {
        int r = nd[t];
        float g = gather_w(csr1, off1[r], off1[r + 1], w, nxt, lane);
        if (csr2) g += gather_w(csr2, off2[r], off2[r + 1], w, nxt, lane);
        size_t o = (size_t)r * D + lane;
        val[t] = base[o] + nxt[o] + __ldg(&w[r]) * g;
    }
    float pp = val[0] * val[1], nn = val[0] * val[2];
    #pragma unroll
    for (int o = 16; o; o >>= 1) {
        pp += __shfl_xor_sync(0xffffffffu, pp, o);
        nn += __shfl_xor_sync(0xffffffffu, nn, o);
    }
    if (lane == 0) {
        outp[wp] = fmaxf(pp * (1.f / 9.f), 0.f);
        outn[wp] = fmaxf(nn * (1.f / 9.f), 0.f);
    }
}

// ---------------------------------------------------------------------------
// Scoring / losses
// ---------------------------------------------------------------------------
__global__ void k_scores_aux(const float* __restrict__ emb,
                             const int* __restrict__ batch, int B, int nu, int idx,
                             float* __restrict__ outp, float* __restrict__ outn) {
    __shared__ float sh[8];
    int warp = (blockIdx.x * blockDim.x + threadIdx.x) >> 5;
    int lane = threadIdx.x & 31;
    int wid  = threadIdx.x >> 5;
    float val = 0.f;
    if (warp < B) {
        const int* row = batch + (size_t)warp * 9;
        int u = row[0], p = row[1], n = row[2];
        float eu = emb[(size_t)u * D + lane];
        float pp = eu * emb[(size_t)(nu + p) * D + lane];
        float nn = eu * emb[(size_t)(nu + n) * D + lane];
        // aux BPR row for this idx
        const int* arow = row + (1 + idx) * 3;
        int au = arow[0], ap = arow[1], an = arow[2];
        float ea = emb[(size_t)au * D + lane];
        float ps = ea * emb[(size_t)(nu + ap) * D + lane];
        float ns = ea * emb[(size_t)(nu + an) * D + lane];
        #pragma unroll
        for (int o = 16; o; o >>= 1) {
            pp += __shfl_xor_sync(0xffffffffu, pp, o);
            nn += __shfl_xor_sync(0xffffffffu, nn, o);
            ps += __shfl_xor_sync(0xffffffffu, ps, o);
            ns += __shfl_xor_sync(0xffffffffu, ns, o);
        }
        if (lane == 0) {
            outp[warp] = fmaxf(pp, 0.f);
            outn[warp] = fmaxf(nn, 0.f);
        }
        val = logsig(ps - ns);
    }
    if (lane == 0) sh[wid] = val;
    __syncthreads();
    if (threadIdx.x < 32) {
        float v = (threadIdx.x < (blockDim.x >> 5)) ? sh[threadIdx.x] : 0.f;
        #pragma unroll
        for (int o = 16; o; o >>= 1) v += __shfl_xor_sync(0xffffffffu, v, o);
        if (threadIdx.x == 0) atomicAdd(&g_scal[idx], v);
    }
}

__global__ void k_sumsq(const float* __restrict__ x, int n, int slot) {
    __shared__ float sh[8];
    float local = 0.f;
    for (int i = blockIdx.x * blockDim.x + threadIdx.x; i < n; i += gridDim.x * blockDim.x) {
        float v = x[i];
        local += v * v;
    }
    int lane = threadIdx.x & 31, wid = threadIdx.x >> 5;
    #pragma unroll
    for (int o = 16; o; o >>= 1) local += __shfl_xor_sync(0xffffffffu, local, o);
    if (lane == 0) sh[wid] = local;
    __syncthreads();
    if (threadIdx.x < 32) {
        float v = (threadIdx.x < (blockDim.x >> 5)) ? sh[threadIdx.x] : 0.f;
        #pragma unroll
        for (int o = 16; o; o >>= 1) v += __shfl_xor_sync(0xffffffffu, v, o);
        if (threadIdx.x == 0) atomicAdd(&g_scal[slot], v);
    }
}

__global__ void k_final(int B, int ni, float* __restrict__ out) {
    __shared__ float sh[8];
    float local = 0.f;
    for (int b = threadIdx.x; b < B; b += blockDim.x) {
        float cp0 = g_sc[ 0 * BMAX + b], cp1 = g_sc[ 1 * BMAX + b];
        float cn0 = g_sc[ 2 * BMAX + b], cn1 = g_sc[ 3 * BMAX + b];
        float ap0 = g_sc[ 4 * BMAX + b], ap1 = g_sc[ 5 * BMAX + b];
        float an0 = g_sc[ 6 * BMAX + b], an1 = g_sc[ 7 * BMAX + b];
        float dp0 = g_sc[ 8 * BMAX + b], dp1 = g_sc[ 9 * BMAX + b];
        float dn0 = g_sc[10 * BMAX + b], dn1 = g_sc[11 * BMAX + b];
        float ps = (dp0 + dp1) * (cp0 * ap0 + cp1 * ap1);
        float ns = (dn0 + dn1) * (cn0 * an0 + cn1 * an1);
        local += logsig(ps - ns);
    }
    int lane = threadIdx.x & 31, wid = threadIdx.x >> 5;
    #pragma unroll
    for (int o = 16; o; o >>= 1) local += __shfl_xor_sync(0xffffffffu, local, o);
    if (lane == 0) sh[wid] = local;
    __syncthreads();
    if (threadIdx.x == 0) {
        float s = 0.f;
        for (int i = 0; i < (int)(blockDim.x >> 5); i++) s += sh[i];
        float rec  = -s / (float)B;
        float aux  = -(g_scal[0] + g_scal[1]) / (2.f * (float)B);
        float embl = (sqrtf(g_scal[2]) + sqrtf(g_scal[3])) / (float)ni;
        out[0] = rec + 0.5f * aux + 1e-4f * embl;
    }
}

// ---------------------------------------------------------------------------
// Host orchestration (graph-capturable)
// ---------------------------------------------------------------------------
#define TB 256
static inline int nblk(long long n) { return (int)((n + TB - 1) / TB); }

extern "C" void kernel_launch(void* const* d_in, const int* in_sizes, int n_in,
                              void* d_out, int out_size) {
    const float* user  = (const float*)d_in[0];
    const float* item  = (const float*)d_in[1];
    const int*   batch = (const int*)  d_in[2];
    const int2*  aux   = (const int2*) d_in[3];
    const int2*  tgt   = (const int2*) d_in[4];

    const int nu   = in_sizes[0] / D;
    const int ni   = in_sizes[1] / D;
    const int ntot = nu + ni;
    const int B    = in_sizes[2] / 9;
    const int Ea   = in_sizes[3] / 4;
    const int Et   = in_sizes[4] / 2;

    float *emb, *pc0, *pc1, *pt0, *pt1, *a0, *a1, *dnv, *sc;
    int *degi, *off, *curs, *csr;
    void* p;
    cudaGetSymbolAddress(&p, g_emb);  emb = (float*)p;
    cudaGetSymbolAddress(&p, g_pc0);  pc0 = (float*)p;
    cudaGetSymbolAddress(&p, g_pc1);  pc1 = (float*)p;
    cudaGetSymbolAddress(&p, g_pt0);  pt0 = (float*)p;
    cudaGetSymbolAddress(&p, g_pt1);  pt1 = (float*)p;
    cudaGetSymbolAddress(&p, g_a0);   a0  = (float*)p;
    cudaGetSymbolAddress(&p, g_a1);   a1  = (float*)p;
    cudaGetSymbolAddress(&p, g_dnv);  dnv = (float*)p;
    cudaGetSymbolAddress(&p, g_sc);   sc  = (float*)p;
    cudaGetSymbolAddress(&p, g_degi); degi = (int*)p;
    cudaGetSymbolAddress(&p, g_off);  off  = (int*)p;
    cudaGetSymbolAddress(&p, g_curs); curs = (int*)p;
    cudaGetSymbolAddress(&p, g_csr);  csr  = (int*)p;
    void* scalp; cudaGetSymbolAddress(&scalp, g_scal);

    const float* wC0 = dnv + 0 * NTOT_C;
    const float* wC1 = dnv + 1 * NTOT_C;
    const float* wA0 = dnv + 2 * NTOT_C;
    const float* wA1 = dnv + 3 * NTOT_C;
    const float* wT  = dnv + 4 * NTOT_C;

    // init
    cudaMemcpyAsync(emb, user, (size_t)nu * D * sizeof(float), cudaMemcpyDeviceToDevice, 0);
    cudaMemcpyAsync(emb + (size_t)nu * D, item, (size_t)ni * D * sizeof(float),
                    cudaMemcpyDeviceToDevice, 0);
    cudaMemsetAsync(scalp, 0, 4 * sizeof(float), 0);
    k_sumsq<<<1024, TB>>>(user, nu * D, 2);
    k_sumsq<<<1024, TB>>>(item, ni * D, 3);

    // degrees: aux0 -> slot0, aux1 -> slot1, tgt -> slot2
    cudaMemsetAsync(degi, 0, 3 * NTOT_C * sizeof(int), 0);
    k_degi<<<nblk(Ea), TB>>>(aux,      Ea, degi + 0 * NTOT_C, nu);
    k_degi<<<nblk(Ea), TB>>>(aux + Ea, Ea, degi + 1 * NTOT_C, nu);
    k_degi<<<nblk(Et), TB>>>(tgt,      Et, degi + 2 * NTOT_C, nu);
    k_dinv5<<<nblk(NTOT_C), TB>>>();

    // offsets (3 structure graphs)
    dim3 gScan(NBLK_SCAN, 3);
    k_scanA<<<gScan, SCAN_B>>>();
    k_scanB<<<3, 1024>>>(NBLK_SCAN);
    k_scanC<<<gScan, SCAN_B>>>();
    cudaMemcpyAsync(curs, off, 3 * NOFF * sizeof(int), cudaMemcpyDeviceToDevice, 0);

    // CSR fill (index-only)
    const long long bA0 = 0, bA1 = 2LL * Ea, bT = 4LL * Ea;
    const int* offA0 = off + 0 * NOFF;
    const int* offA1 = off + 1 * NOFF;
    const int* offT  = off + 2 * NOFF;
    k_fill<<<nblk(Ea), TB>>>(aux,      Ea, curs + 0 * NOFF, csr + bA0, nu);
    k_fill<<<nblk(Ea), TB>>>(aux + Ea, Ea, curs + 1 * NOFF, csr + bA1, nu);
    k_fill<<<nblk(Et), TB>>>(tgt,      Et, curs + 2 * NOFF, csr + bT,  nu);

    const int gcnB = nblk((long long)ntot * 32);
    const int sblk = nblk((long long)B * 32);
    const int n4   = ntot * D / 4;

    // layer-1 passes (dual-weight fused)
    k_dual_w<<<gcnB, TB>>>(csr + bA0, offA0, emb, wC0, wA0, pc0, a0, ntot);
    k_dual_w<<<gcnB, TB>>>(csr + bA1, offA1, emb, wC1, wA1, pc1, a1, ntot);
    k_dual_w<<<gcnB, TB>>>(csr + bT,  offT,  emb, wC0, wC1, pt0, pt1, ntot);
    k_add<<<nblk(n4), TB>>>(pc0, pt0, n4);   // comb0 layer1
    k_add<<<nblk(n4), TB>>>(pc1, pt1, n4);   // comb1 layer1

    // comb scoring (sparse layer2 over aux CSR + tgt CSR)
    k_score2<<<sblk, TB>>>(csr + bA0, offA0, csr + bT, offT, wC0, pc0, emb,
                           batch, B, nu, sc + 0 * BMAX, sc + 2 * BMAX);
    k_score2<<<sblk, TB>>>(csr + bA1, offA1, csr + bT, offT, wC1, pc1, emb,
                           batch, B, nu, sc + 1 * BMAX, sc + 3 * BMAX);

    // aux layer2 -> ae (dense, needed for de); reuse pt buffers
    float* ae0 = pt0;
    float* ae1 = pt1;
    k_gcn_w<<<gcnB, TB>>>(csr + bA0, offA0, wA0, a0, emb, ae0, ntot);
    k_gcn_w<<<gcnB, TB>>>(csr + bA1, offA1, wA1, a1, emb, ae1, ntot);
    k_scores_aux<<<sblk, TB>>>(ae0, batch, B, nu, 0, sc + 4 * BMAX, sc + 6 * BMAX);
    k_scores_aux<<<sblk, TB>>>(ae1, batch, B, nu, 1, sc + 5 * BMAX, sc + 7 * BMAX);

    // de layer1 over tgt for both idx (dual-src fused); reuse a buffers
    float* d0 = a0;
    float* d1 = a1;
    k_dual_s<<<gcnB, TB>>>(csr + bT, offT, ae0, ae1, wT, d0, d1, ntot);

    // de scoring (sparse layer2 over tgt CSR)
    k_score2<<<sblk, TB>>>(csr + bT, offT, (const int*)0, (const int*)0, wT, d0, ae0,
                           batch, B, nu, sc + 8 * BMAX, sc + 10 * BMAX);
    k_score2<<<sblk, TB>>>(csr + bT, offT, (const int*)0, (const int*)0, wT, d1, ae1,
                           batch, B, nu, sc + 9 * BMAX, sc + 11 * BMAX);

    k_final<<<1, TB>>>(B, ni, (float*)d_out);
}

// round 5
// speedup vs baseline: 1.9367x; 1.2040x over previous
#include <cuda_runtime.h>
#include <math.h>

// ---------------------------------------------------------------------------
// Shapes
// ---------------------------------------------------------------------------
#define D        32
#define NU_C     100001
#define NI_C     50001
#define NTOT_C   (NU_C + NI_C)          // 150002
#define NOFF     (NTOT_C + 1)
#define BMAX     4096
#define SCAN_B   256
#define NBLK_SCAN ((NOFF + SCAN_B - 1) / SCAN_B)
#define SUMS_STRIDE 640
#define CSR_CAP  6400000

// ---------------------------------------------------------------------------
// Device scratch
// ---------------------------------------------------------------------------
__device__ float g_emb[NTOT_C * D];
__device__ float g_pc0[NTOT_C * D];     // comb0 layer1
__device__ float g_pc1[NTOT_C * D];     // comb1 layer1
__device__ float g_ae0[NTOT_C * D];     // ae0
__device__ float g_ae1[NTOT_C * D];     // ae1
__device__ float g_a0 [NTOT_C * D];     // aux0 layer1; later de0 layer1
__device__ float g_a1 [NTOT_C * D];     // aux1 layer1; later de1 layer1
__device__ int   g_degi [3 * NTOT_C];   // aux0, aux1, tgt
__device__ float g_dnv  [5 * NTOT_C];   // c0, c1, a0, a1, t
__device__ int   g_off  [3 * NOFF];
__device__ int   g_curs [3 * NOFF];
__device__ int   g_bsums[3 * SUMS_STRIDE];
__device__ int   g_csr  [CSR_CAP];
// score slots: CP=0 CN=1 AP=2 AN=3 DP=4 DN=5; offset = (slot*2 + idx)*BMAX + b
__device__ float g_sc  [12 * BMAX];
__device__ float g_scal[4];

// ---------------------------------------------------------------------------
// Helpers
// ---------------------------------------------------------------------------
__device__ __forceinline__ float logsig(float x) {
    return (x >= 0.f) ? -log1pf(expf(-x)) : (x - log1pf(expf(x)));
}

__device__ __forceinline__ float gather_w(const int* __restrict__ csr,
                                          int k, int end,
                                          const float* __restrict__ dnv,
                                          const float* __restrict__ src,
                                          int lane) {
    float acc = 0.f;
    for (; k + 8 <= end; k += 8) {
        int e[8]; float w[8];
        #pragma unroll
        for (int j = 0; j < 8; j++) e[j] = __ldg(&csr[k + j]);
        #pragma unroll
        for (int j = 0; j < 8; j++) w[j] = __ldg(&dnv[e[j]]);
        #pragma unroll
        for (int j = 0; j < 8; j++)
            acc = fmaf(w[j], __ldg(&src[(size_t)e[j] * D + lane]), acc);
    }
    for (; k < end; k++) {
        int e = __ldg(&csr[k]);
        acc = fmaf(__ldg(&dnv[e]), __ldg(&src[(size_t)e * D + lane]), acc);
    }
    return acc;
}

// ---------------------------------------------------------------------------
// Graph build (fused over all 3 edge segments)
// ---------------------------------------------------------------------------
__global__ void k_deg3(const int2* __restrict__ aux, const int2* __restrict__ tgt,
                       int Ea, int Et, int nu) {
    int t = blockIdx.x * blockDim.x + threadIdx.x;
    int2 ed; int slot;
    if (t < 2 * Ea)            { ed = aux[t];          slot = (t < Ea) ? 0 : 1; }
    else if (t < 2 * Ea + Et)  { ed = tgt[t - 2 * Ea]; slot = 2; }
    else return;
    int* deg = g_degi + slot * NTOT_C;
    atomicAdd(&deg[ed.x], 1);
    atomicAdd(&deg[nu + ed.y], 1);
}

__global__ void k_dinv5() {
    int i = blockIdx.x * blockDim.x + threadIdx.x;
    if (i >= NTOT_C) return;
    int d0 = g_degi[0 * NTOT_C + i];
    int d1 = g_degi[1 * NTOT_C + i];
    int dt = g_degi[2 * NTOT_C + i];
    int dd[5] = {d0 + dt, d1 + dt, d0, d1, dt};
    #pragma unroll
    for (int s = 0; s < 5; s++)
        g_dnv[s * NTOT_C + i] = (dd[s] > 0) ? rsqrtf((float)dd[s]) : 0.f;
}

__global__ void k_scanA() {
    int g = blockIdx.y;
    const int* deg = g_degi + g * NTOT_C;
    int* out  = g_off   + g * NOFF;
    int* sums = g_bsums + g * SUMS_STRIDE;
    int idx = blockIdx.x * SCAN_B + threadIdx.x;
    int val = (idx < NTOT_C) ? deg[idx] : 0;
    int lane = threadIdx.x & 31, wid = threadIdx.x >> 5;
    int x = val;
    #pragma unroll
    for (int o = 1; o < 32; o <<= 1) {
        int y = __shfl_up_sync(0xffffffffu, x, o);
        if (lane >= o) x += y;
    }
    __shared__ int ws[8], wbase[8];
    if (lane == 31) ws[wid] = x;
    __syncthreads();
    if (threadIdx.x == 0) {
        int s = 0;
        for (int i = 0; i < 8; i++) { wbase[i] = s; s += ws[i]; }
    }
    __syncthreads();
    int incl = x + wbase[wid];
    if (idx < NOFF) out[idx] = incl - val;
    if (threadIdx.x == SCAN_B - 1) sums[blockIdx.x] = incl;
}

__global__ void k_scanB(int nb) {
    int g = blockIdx.x;
    int* sums = g_bsums + g * SUMS_STRIDE;
    __shared__ int sh[SUMS_STRIDE];
    int tid = threadIdx.x;
    int orig = 0;
    if (tid < nb) { orig = sums[tid]; sh[tid] = orig; }
    __syncthreads();
    for (int o = 1; o < nb; o <<= 1) {
        int v = 0;
        if (tid < nb && tid >= o) v = sh[tid - o];
        __syncthreads();
        if (tid < nb && tid >= o) sh[tid] += v;
        __syncthreads();
    }
    if (tid < nb) sums[tid] = sh[tid] - orig;
}

__global__ void k_scanC() {
    int g = blockIdx.y;
    int idx = blockIdx.x * SCAN_B + threadIdx.x;
    if (idx < NOFF)
        g_off[g * NOFF + idx] += g_bsums[g * SUMS_STRIDE + blockIdx.x];
}

__global__ void k_fill3(const int2* __restrict__ aux, const int2* __restrict__ tgt,
                        int Ea, int Et, int nu) {
    int t = blockIdx.x * blockDim.x + threadIdx.x;
    int2 ed; int slot; long long base;
    if (t < 2 * Ea) {
        ed = aux[t];
        slot = (t < Ea) ? 0 : 1;
        base = (t < Ea) ? 0 : 2LL * Ea;
    } else if (t < 2 * Ea + Et) {
        ed = tgt[t - 2 * Ea]; slot = 2; base = 4LL * Ea;
    } else return;
    int* curs = g_curs + slot * NOFF;
    int* csr  = g_csr + base;
    int u = ed.x, v = nu + ed.y;
    csr[atomicAdd(&curs[u], 1)] = v;
    csr[atomicAdd(&curs[v], 1)] = u;
}

// ---------------------------------------------------------------------------
// Propagation
// ---------------------------------------------------------------------------
// one edge list, one src, two weight vectors -> two outputs; optional +=
__global__ void __launch_bounds__(256)
k_dual_w(const int* __restrict__ csr, const int* __restrict__ off,
         const float* __restrict__ src,
         const float* __restrict__ wX, const float* __restrict__ wY,
         float* __restrict__ outX, float* __restrict__ outY, int ntot, int accum) {
    int u = (blockIdx.x * blockDim.x + threadIdx.x) >> 5;
    if (u >= ntot) return;
    int lane = threadIdx.x & 31;
    int k = off[u], end = off[u + 1];
    float accX = 0.f, accY = 0.f;
    for (; k + 8 <= end; k += 8) {
        int e[8]; float x[8], y[8];
        #pragma unroll
        for (int j = 0; j < 8; j++) e[j] = __ldg(&csr[k + j]);
        #pragma unroll
        for (int j = 0; j < 8; j++) { x[j] = __ldg(&wX[e[j]]); y[j] = __ldg(&wY[e[j]]); }
        #pragma unroll
        for (int j = 0; j < 8; j++) {
            float v = __ldg(&src[(size_t)e[j] * D + lane]);
            accX = fmaf(x[j], v, accX);
            accY = fmaf(y[j], v, accY);
        }
    }
    for (; k < end; k++) {
        int e = __ldg(&csr[k]);
        float v = __ldg(&src[(size_t)e * D + lane]);
        accX = fmaf(__ldg(&wX[e]), v, accX);
        accY = fmaf(__ldg(&wY[e]), v, accY);
    }
    size_t o = (size_t)u * D + lane;
    float rx = __ldg(&wX[u]) * accX;
    float ry = __ldg(&wY[u]) * accY;
    if (accum) { rx += outX[o]; ry += outY[o]; }
    outX[o] = rx;
    outY[o] = ry;
}

// one edge list, one weight vector, two srcs -> two outputs (de layer1)
__global__ void __launch_bounds__(256)
k_dual_s(const int* __restrict__ csr, const int* __restrict__ off,
         const float* __restrict__ s0, const float* __restrict__ s1,
         const float* __restrict__ w,
         float* __restrict__ o0, float* __restrict__ o1, int ntot) {
    int u = (blockIdx.x * blockDim.x + threadIdx.x) >> 5;
    if (u >= ntot) return;
    int lane = threadIdx.x & 31;
    int k = off[u], end = off[u + 1];
    float a0 = 0.f, a1 = 0.f;
    for (; k + 4 <= end; k += 4) {
        int e[4]; float wj[4];
        #pragma unroll
        for (int j = 0; j < 4; j++) e[j] = __ldg(&csr[k + j]);
        #pragma unroll
        for (int j = 0; j < 4; j++) wj[j] = __ldg(&w[e[j]]);
        #pragma unroll
        for (int j = 0; j < 4; j++) {
            size_t ro = (size_t)e[j] * D + lane;
            a0 = fmaf(wj[j], __ldg(&s0[ro]), a0);
            a1 = fmaf(wj[j], __ldg(&s1[ro]), a1);
        }
    }
    for (; k < end; k++) {
        int e = __ldg(&csr[k]);
        float wj = __ldg(&w[e]);
        size_t ro = (size_t)e * D + lane;
        a0 = fmaf(wj, __ldg(&s0[ro]), a0);
        a1 = fmaf(wj, __ldg(&s1[ro]), a1);
    }
    size_t o = (size_t)u * D + lane;
    float wu = __ldg(&w[u]);
    o0[o] = wu * a0;
    o1[o] = wu * a1;
}

// aux layer2 + layer-mean
__global__ void __launch_bounds__(256)
k_gcn_w(const int* __restrict__ csr, const int* __restrict__ off,
        const float* __restrict__ w,
        const float* __restrict__ src, const float* __restrict__ base,
        float* __restrict__ out, int ntot) {
    int u = (blockIdx.x * blockDim.x + threadIdx.x) >> 5;
    if (u >= ntot) return;
    int lane = threadIdx.x & 31;
    float acc = gather_w(csr, off[u], off[u + 1], w, src, lane);
    size_t o = (size_t)u * D + lane;
    out[o] = (__ldg(&w[u]) * acc + src[o] + base[o]) * (1.f / 3.f);
}

// comb scoring: sparse layer2 over (aux csr + tgt csr); blockIdx.y selects idx
__global__ void k_score_comb(const int* __restrict__ csrA0, const int* __restrict__ offA0,
                             const int* __restrict__ csrA1, const int* __restrict__ offA1,
                             const int* __restrict__ csrT, const int* __restrict__ offT,
                             const float* __restrict__ w0, const float* __restrict__ w1,
                             const float* __restrict__ nxt0, const float* __restrict__ nxt1,
                             const float* __restrict__ base,
                             const int* __restrict__ batch, int B, int nu) {
    int which = blockIdx.y;
    const int* csrA = which ? csrA1 : csrA0;
    const int* offA = which ? offA1 : offA0;
    const float* w   = which ? w1 : w0;
    const float* nxt = which ? nxt1 : nxt0;
    int wp = (blockIdx.x * blockDim.x + threadIdx.x) >> 5;
    if (wp >= B) return;
    int lane = threadIdx.x & 31;
    const int* row = batch + (size_t)wp * 9;
    int nd[3] = {row[0], nu + row[1], nu + row[2]};
    float val[3];
    #pragma unroll
    for (int t = 0; t < 3; t++) {
        int r = nd[t];
        float g = gather_w(csrA, offA[r], offA[r + 1], w, nxt, lane)
                + gather_w(csrT, offT[r], offT[r + 1], w, nxt, lane);
        size_t o = (size_t)r * D + lane;
        val[t] = base[o] + nxt[o] + __ldg(&w[r]) * g;
    }
    float pp = val[0] * val[1], nn = val[0] * val[2];
    #pragma unroll
    for (int o = 16; o; o >>= 1) {
        pp += __shfl_xor_sync(0xffffffffu, pp, o);
        nn += __shfl_xor_sync(0xffffffffu, nn, o);
    }
    if (lane == 0) {
        g_sc[(0 * 2 + which) * BMAX + wp] = fmaxf(pp * (1.f / 9.f), 0.f);
        g_sc[(1 * 2 + which) * BMAX + wp] = fmaxf(nn * (1.f / 9.f), 0.f);
    }
}

// de scoring for both idx: sparse layer2 over tgt csr, dual source
__global__ void k_score_de(const int* __restrict__ csrT, const int* __restrict__ offT,
                           const float* __restrict__ wT,
                           const float* __restrict__ d0, const float* __restrict__ d1,
                           const float* __restrict__ ae0, const float* __restrict__ ae1,
                           const int* __restrict__ batch, int B, int nu) {
    int wp = (blockIdx.x * blockDim.x + threadIdx.x) >> 5;
    if (wp >= B) return;
    int lane = threadIdx.x & 31;
    const int* row = batch + (size_t)wp * 9;
    int nd[3] = {row[0], nu + row[1], nu + row[2]};
    float v0[3], v1[3];
    #pragma unroll
    for (int t = 0; t < 3; t++) {
        int r = nd[t];
        int k = offT[r], end = offT[r + 1];
        float a0 = 0.f, a1 = 0.f;
        for (; k + 4 <= end; k += 4) {
            int e[4]; float wj[4];
            #pragma unroll
            for (int j = 0; j < 4; j++) e[j] = __ldg(&csrT[k + j]);
            #pragma unroll
            for (int j = 0; j < 4; j++) wj[j] = __ldg(&wT[e[j]]);
            #pragma unroll
            for (int j = 0; j < 4; j++) {
                size_t ro = (size_t)e[j] * D + lane;
                a0 = fmaf(wj[j], __ldg(&d0[ro]), a0);
                a1 = fmaf(wj[j], __ldg(&d1[ro]), a1);
            }
        }
        for (; k < end; k++) {
            int e = __ldg(&csrT[k]);
            float wj = __ldg(&wT[e]);
            size_t ro = (size_t)e * D + lane;
            a0 = fmaf(wj, __ldg(&d0[ro]), a0);
            a1 = fmaf(wj, __ldg(&d1[ro]), a1);
        }
        size_t o = (size_t)r * D + lane;
        float wr = __ldg(&wT[r]);
        v0[t] = ae0[o] + d0[o] + wr * a0;
        v1[t] = ae1[o] + d1[o] + wr * a1;
    }
    float pp0 = v0[0] * v0[1], nn0 = v0[0] * v0[2];
    float pp1 = v1[0] * v1[1], nn1 = v1[0] * v1[2];
    #pragma unroll
    for (int o = 16; o; o >>= 1) {
        pp0 += __shfl_xor_sync(0xffffffffu, pp0, o);
        nn0 += __shfl_xor_sync(0xffffffffu, nn0, o);
        pp1 += __shfl_xor_sync(0xffffffffu, pp1, o);
        nn1 += __shfl_xor_sync(0xffffffffu, nn1, o);
    }
    if (lane == 0) {
        g_sc[ 8 * BMAX + wp] = fmaxf(pp0 * (1.f / 9.f), 0.f);
        g_sc[10 * BMAX + wp] = fmaxf(nn0 * (1.f / 9.f), 0.f);
        g_sc[ 9 * BMAX + wp] = fmaxf(pp1 * (1.f / 9.f), 0.f);
        g_sc[11 * BMAX + wp] = fmaxf(nn1 * (1.f / 9.f), 0.f);
    }
}

// AP/AN + aux BPR for both idx in one launch
__global__ void k_scores_aux2(const float* __restrict__ ae0, const float* __restrict__ ae1,
                              const int* __restrict__ batch, int B, int nu) {
    __shared__ float sh0[8], sh1[8];
    int warp = (blockIdx.x * blockDim.x + threadIdx.x) >> 5;
    int lane = threadIdx.x & 31;
    int wid  = threadIdx.x >> 5;
    float val0 = 0.f, val1 = 0.f;
    if (warp < B) {
        const int* row = batch + (size_t)warp * 9;
        int u = row[0], p = nu + row[1], n = nu + row[2];
        size_t ou = (size_t)u * D + lane, op = (size_t)p * D + lane, on = (size_t)n * D + lane;
        float e0u = ae0[ou], e1u = ae1[ou];
        float pp0 = e0u * ae0[op], nn0 = e0u * ae0[on];
        float pp1 = e1u * ae1[op], nn1 = e1u * ae1[on];
        const int* r0 = row + 3;
        const int* r1 = row + 6;
        float a0u = ae0[(size_t)r0[0] * D + lane];
        float ps0 = a0u * ae0[(size_t)(nu + r0[1]) * D + lane];
        float ns0 = a0u * ae0[(size_t)(nu + r0[2]) * D + lane];
        float a1u = ae1[(size_t)r1[0] * D + lane];
        float ps1 = a1u * ae1[(size_t)(nu + r1[1]) * D + lane];
        float ns1 = a1u * ae1[(size_t)(nu + r1[2]) * D + lane];
        #pragma unroll
        for (int o = 16; o; o >>= 1) {
            pp0 += __shfl_xor_sync(0xffffffffu, pp0, o);
            nn0 += __shfl_xor_sync(0xffffffffu, nn0, o);
            pp1 += __shfl_xor_sync(0xffffffffu, pp1, o);
            nn1 += __shfl_xor_sync(0xffffffffu, nn1, o);
            ps0 += __shfl_xor_sync(0xffffffffu, ps0, o);
            ns0 += __shfl_xor_sync(0xffffffffu, ns0, o);
            ps1 += __shfl_xor_sync(0xffffffffu, ps1, o);
            ns1 += __shfl_xor_sync(0xffffffffu, ns1, o);
        }
        if (lane == 0) {
            g_sc[4 * BMAX + warp] = fmaxf(pp0, 0.f);
            g_sc[6 * BMAX + warp] = fmaxf(nn0, 0.f);
            g_sc[5 * BMAX + warp] = fmaxf(pp1, 0.f);
            g_sc[7 * BMAX + warp] = fmaxf(nn1, 0.f);
        }
        val0 = logsig(ps0 - ns0);
        val1 = logsig(ps1 - ns1);
    }
    if (lane == 0) { sh0[wid] = val0; sh1[wid] = val1; }
    __syncthreads();
    if (threadIdx.x < 32) {
        float v0 = (threadIdx.x < (blockDim.x >> 5)) ? sh0[threadIdx.x] : 0.f;
        float v1 = (threadIdx.x < (blockDim.x >> 5)) ? sh1[threadIdx.x] : 0.f;
        #pragma unroll
        for (int o = 16; o; o >>= 1) {
            v0 += __shfl_xor_sync(0xffffffffu, v0, o);
            v1 += __shfl_xor_sync(0xffffffffu, v1, o);
        }
        if (threadIdx.x == 0) {
            atomicAdd(&g_scal[0], v0);
            atomicAdd(&g_scal[1], v1);
        }
    }
}

// sumsq for user (y=0) and item (y=1) in one launch
__global__ void k_sumsq2(const float* __restrict__ u, int nuD,
                         const float* __restrict__ it, int niD) {
    __shared__ float sh[8];
    const float* x = blockIdx.y ? it : u;
    int n = blockIdx.y ? niD : nuD;
    int slot = blockIdx.y ? 3 : 2;
    float local = 0.f;
    for (int i = blockIdx.x * blockDim.x + threadIdx.x; i < n; i += gridDim.x * blockDim.x) {
        float v = x[i];
        local += v * v;
    }
    int lane = threadIdx.x & 31, wid = threadIdx.x >> 5;
    #pragma unroll
    for (int o = 16; o; o >>= 1) local += __shfl_xor_sync(0xffffffffu, local, o);
    if (lane == 0) sh[wid] = local;
    __syncthreads();
    if (threadIdx.x < 32) {
        float v = (threadIdx.x < (blockDim.x >> 5)) ? sh[threadIdx.x] : 0.f;
        #pragma unroll
        for (int o = 16; o; o >>= 1) v += __shfl_xor_sync(0xffffffffu, v, o);
        if (threadIdx.x == 0) atomicAdd(&g_scal[slot], v);
    }
}

__global__ void k_final(int B, int ni, float* __restrict__ out) {
    __shared__ float sh[8];
    float local = 0.f;
    for (int b = threadIdx.x; b < B; b += blockDim.x) {
        float cp0 = g_sc[ 0 * BMAX + b], cp1 = g_sc[ 1 * BMAX + b];
        float cn0 = g_sc[ 2 * BMAX + b], cn1 = g_sc[ 3 * BMAX + b];
        float ap0 = g_sc[ 4 * BMAX + b], ap1 = g_sc[ 5 * BMAX + b];
        float an0 = g_sc[ 6 * BMAX + b], an1 = g_sc[ 7 * BMAX + b];
        float dp0 = g_sc[ 8 * BMAX + b], dp1 = g_sc[ 9 * BMAX + b];
        float dn0 = g_sc[10 * BMAX + b], dn1 = g_sc[11 * BMAX + b];
        float ps = (dp0 + dp1) * (cp0 * ap0 + cp1 * ap1);
        float ns = (dn0 + dn1) * (cn0 * an0 + cn1 * an1);
        local += logsig(ps - ns);
    }
    int lane = threadIdx.x & 31, wid = threadIdx.x >> 5;
    #pragma unroll
    for (int o = 16; o; o >>= 1) local += __shfl_xor_sync(0xffffffffu, local, o);
    if (lane == 0) sh[wid] = local;
    __syncthreads();
    if (threadIdx.x == 0) {
        float s = 0.f;
        for (int i = 0; i < (int)(blockDim.x >> 5); i++) s += sh[i];
        float rec  = -s / (float)B;
        float aux  = -(g_scal[0] + g_scal[1]) / (2.f * (float)B);
        float embl = (sqrtf(g_scal[2]) + sqrtf(g_scal[3])) / (float)ni;
        out[0] = rec + 0.5f * aux + 1e-4f * embl;
    }
}

// ---------------------------------------------------------------------------
// Host orchestration (graph-capturable, fork/join dual stream)
// ---------------------------------------------------------------------------
#define TB 256
static inline int nblk(long long n) { return (int)((n + TB - 1) / TB); }

extern "C" void kernel_launch(void* const* d_in, const int* in_sizes, int n_in,
                              void* d_out, int out_size) {
    static cudaStream_t s1 = 0;
    static cudaEvent_t e0 = 0, e1 = 0, e2 = 0, e3 = 0;
    if (!s1) {
        cudaStreamCreateWithFlags(&s1, cudaStreamNonBlocking);
        cudaEventCreateWithFlags(&e0, cudaEventDisableTiming);
        cudaEventCreateWithFlags(&e1, cudaEventDisableTiming);
        cudaEventCreateWithFlags(&e2, cudaEventDisableTiming);
        cudaEventCreateWithFlags(&e3, cudaEventDisableTiming);
    }

    const float* user  = (const float*)d_in[0];
    const float* item  = (const float*)d_in[1];
    const int*   batch = (const int*)  d_in[2];
    const int2*  aux   = (const int2*) d_in[3];
    const int2*  tgt   = (const int2*) d_in[4];

    const int nu   = in_sizes[0] / D;
    const int ni   = in_sizes[1] / D;
    const int ntot = nu + ni;
    const int B    = in_sizes[2] / 9;
    const int Ea   = in_sizes[3] / 4;
    const int Et   = in_sizes[4] / 2;

    float *emb, *pc0, *pc1, *ae0, *ae1, *a0, *a1, *dnv;
    int *degi, *off, *curs, *csr;
    void* p;
    cudaGetSymbolAddress(&p, g_emb);  emb = (float*)p;
    cudaGetSymbolAddress(&p, g_pc0);  pc0 = (float*)p;
    cudaGetSymbolAddress(&p, g_pc1);  pc1 = (float*)p;
    cudaGetSymbolAddress(&p, g_ae0);  ae0 = (float*)p;
    cudaGetSymbolAddress(&p, g_ae1);  ae1 = (float*)p;
    cudaGetSymbolAddress(&p, g_a0);   a0  = (float*)p;
    cudaGetSymbolAddress(&p, g_a1);   a1  = (float*)p;
    cudaGetSymbolAddress(&p, g_dnv);  dnv = (float*)p;
    cudaGetSymbolAddress(&p, g_degi); degi = (int*)p;
    cudaGetSymbolAddress(&p, g_off);  off  = (int*)p;
    cudaGetSymbolAddress(&p, g_curs); curs = (int*)p;
    cudaGetSymbolAddress(&p, g_csr);  csr  = (int*)p;
    void* scalp; cudaGetSymbolAddress(&scalp, g_scal);

    const float* wC0 = dnv + 0 * NTOT_C;
    const float* wC1 = dnv + 1 * NTOT_C;
    const float* wA0 = dnv + 2 * NTOT_C;
    const float* wA1 = dnv + 3 * NTOT_C;
    const float* wT  = dnv + 4 * NTOT_C;

    // ---- init + fork sumsq to side stream ----
    cudaMemsetAsync(scalp, 0, 4 * sizeof(float), 0);
    cudaEventRecord(e0, 0);
    cudaStreamWaitEvent(s1, e0, 0);
    {
        dim3 g(512, 2);
        k_sumsq2<<<g, TB, 0, s1>>>(user, nu * D, item, ni * D);
    }
    cudaMemcpyAsync(emb, user, (size_t)nu * D * sizeof(float), cudaMemcpyDeviceToDevice, 0);
    cudaMemcpyAsync(emb + (size_t)nu * D, item, (size_t)ni * D * sizeof(float),
                    cudaMemcpyDeviceToDevice, 0);

    // ---- build ----
    cudaMemsetAsync(degi, 0, 3 * NTOT_C * sizeof(int), 0);
    k_deg3<<<nblk(2LL * Ea + Et), TB>>>(aux, tgt, Ea, Et, nu);
    k_dinv5<<<nblk(NTOT_C), TB>>>();
    dim3 gScan(NBLK_SCAN, 3);
    k_scanA<<<gScan, SCAN_B>>>();
    k_scanB<<<3, 1024>>>(NBLK_SCAN);
    k_scanC<<<gScan, SCAN_B>>>();
    cudaMemcpyAsync(curs, off, 3 * NOFF * sizeof(int), cudaMemcpyDeviceToDevice, 0);
    k_fill3<<<nblk(2LL * Ea + Et), TB>>>(aux, tgt, Ea, Et, nu);

    const long long bA0 = 0, bA1 = 2LL * Ea, bT = 4LL * Ea;
    const int* offA0 = off + 0 * NOFF;
    const int* offA1 = off + 1 * NOFF;
    const int* offT  = off + 2 * NOFF;
    const int gcnB = nblk((long long)ntot * 32);
    const int sblk = nblk((long long)B * 32);

    // ---- layer-1 (dual-weight; tgt pass accumulates into pc) ----
    k_dual_w<<<gcnB, TB>>>(csr + bA0, offA0, emb, wC0, wA0, pc0, a0, ntot, 0);
    k_dual_w<<<gcnB, TB>>>(csr + bA1, offA1, emb, wC1, wA1, pc1, a1, ntot, 0);
    k_dual_w<<<gcnB, TB>>>(csr + bT,  offT,  emb, wC0, wC1, pc0, pc1, ntot, 1);

    // fork comb scoring to side stream
    cudaEventRecord(e1, 0);
    cudaStreamWaitEvent(s1, e1, 0);
    {
        dim3 g(sblk, 2);
        k_score_comb<<<g, TB, 0, s1>>>(csr + bA0, offA0, csr + bA1, offA1,
                                       csr + bT, offT, wC0, wC1, pc0, pc1, emb,
                                       batch, B, nu);
    }

    // ---- aux layer-2 -> ae ----
    k_gcn_w<<<gcnB, TB>>>(csr + bA0, offA0, wA0, a0, emb, ae0, ntot);
    k_gcn_w<<<gcnB, TB>>>(csr + bA1, offA1, wA1, a1, emb, ae1, ntot);

    // fork aux scores to side stream (reads ae0/ae1 only)
    cudaEventRecord(e2, 0);
    cudaStreamWaitEvent(s1, e2, 0);
    k_scores_aux2<<<sblk, TB, 0, s1>>>(ae0, ae1, batch, B, nu);

    // ---- de layer-1 (dual source) + de scoring ----
    float* d0 = a0;
    float* d1 = a1;
    k_dual_s<<<gcnB, TB>>>(csr + bT, offT, ae0, ae1, wT, d0, d1, ntot);
    k_score_de<<<sblk, TB>>>(csr + bT, offT, wT, d0, d1, ae0, ae1, batch, B, nu);

    // ---- join + finalize ----
    cudaEventRecord(e3, s1);
    cudaStreamWaitEvent(0, e3, 0);
    k_final<<<1, TB>>>(B, ni, (float*)d_out);
}